// round 1
// baseline (speedup 1.0000x reference)
#include <cuda_runtime.h>

// Problem constants
static constexpr int Bn    = 2;
static constexpr int Din   = 18;
static constexpr int Dout  = 16;
static constexpr int Hn    = 128;
static constexpr int Wn    = 128;
static constexpr int ROWF  = 125;              // floats per neighborhood row (5*5*5)
static constexpr int VOX   = 128;              // voxels per CTA (= one full W row)
static constexpr int SBUF_WORDS = VOX * ROWF;  // 16000 floats = 64000 B
static constexpr int SX_STRIDE  = 132;         // padded x-row stride (conflict-free)
static constexpr int SX_WORDS   = 9 * SX_STRIDE;
static constexpr int SMEM_BYTES = (SBUF_WORDS + SX_WORDS) * 4;

// Input-stationary 5^3 -> 3^3 valid cross-correlation accumulate.
// 125 LDS + 729 FMA per call, fully unrolled.
__device__ __forceinline__ void conv_acc(const float* __restrict__ s, int base,
                                         const float (&wk)[27], float (&acc)[27]) {
#pragma unroll
    for (int p = 0; p < 5; p++)
#pragma unroll
    for (int q = 0; q < 5; q++)
#pragma unroll
    for (int r = 0; r < 5; r++) {
        float v = s[base + p * 25 + q * 5 + r];
#pragma unroll
        for (int a = 0; a < 3; a++) {
            if (p - a < 0 || p - a > 2) continue;
#pragma unroll
            for (int bq = 0; bq < 3; bq++) {
                if (q - bq < 0 || q - bq > 2) continue;
#pragma unroll
                for (int cr = 0; cr < 3; cr++) {
                    if (r - cr < 0 || r - cr > 2) continue;
                    acc[(a * 3 + bq) * 3 + cr] =
                        fmaf(v, wk[((p - a) * 3 + (q - bq)) * 3 + (r - cr)],
                             acc[(a * 3 + bq) * 3 + cr]);
                }
            }
        }
    }
}

__global__ void __launch_bounds__(VOX, 3)
jbf_kernel(const float* __restrict__ x,
           const float* __restrict__ dom,
           const float* __restrict__ gui,
           const float* __restrict__ dom_w,
           const float* __restrict__ dom_b,
           const float* __restrict__ rng_w,
           const float* __restrict__ rng_b,
           float* __restrict__ out)
{
    extern __shared__ float smem[];
    float* sbuf = smem;                 // [VOX][125] staged neighborhood rows
    float* sx   = smem + SBUF_WORDS;    // [9][SX_STRIDE] padded x rows

    const int tid = threadIdx.x;
    const int cta = blockIdx.x;
    const int h = cta & (Hn - 1);
    const int d = (cta >> 7) & (Dout - 1);
    const int b = cta >> 11;
    const long long m0 = (long long)cta * VOX;

    // ---- Stage x rows: planes d..d+2, rows h-1..h+1, cols -1..128 (zero pad H/W) ----
    for (int idx = tid; idx < 9 * 130; idx += VOX) {
        int ij = idx / 130;
        int wp = idx - ij * 130;        // 0..129  -> w = wp-1
        int i = ij / 3, j = ij % 3;
        int hh = h + j - 1;
        int ww = wp - 1;
        float v = 0.0f;
        if (hh >= 0 && hh < Hn && ww >= 0 && ww < Wn)
            v = x[(((long long)b * Din + (d + i)) << 14) + (hh << 7) + ww];
        sx[ij * SX_STRIDE + wp] = v;
    }

    // ---- Conv weights (domain first) ----
    float wk[27];
#pragma unroll
    for (int t = 0; t < 27; t++) wk[t] = dom_w[t];

    // ---- Phase 1: stage domain rows (coalesced float4), compute domain kernel ----
    {
        const float4* src = (const float4*)(dom + m0 * ROWF);  // 64000B chunk, 16B aligned
        float4* dst = (float4*)sbuf;
        for (int i = tid; i < SBUF_WORDS / 4; i += VOX) dst[i] = src[i];
    }
    __syncthreads();

    float dk[27];
#pragma unroll
    for (int o = 0; o < 27; o++) dk[o] = 0.0f;
    conv_acc(sbuf, tid * ROWF, wk, dk);
    __syncthreads();   // everyone done reading sbuf before restage

    // ---- Phase 2: stage guide rows, compute range kernel ----
    {
        const float4* src = (const float4*)(gui + m0 * ROWF);
        float4* dst = (float4*)sbuf;
        for (int i = tid; i < SBUF_WORDS / 4; i += VOX) dst[i] = src[i];
    }
#pragma unroll
    for (int t = 0; t < 27; t++) wk[t] = rng_w[t];
    __syncthreads();

    float rk[27];
#pragma unroll
    for (int o = 0; o < 27; o++) rk[o] = 0.0f;
    conv_acc(sbuf, tid * ROWF, wk, rk);

    // ---- Fuse: ReLU(conv+b), bilateral weight, weighted x-sum, normalize ----
    const float db = dom_b[0];
    const float rb = rng_b[0];
    float num = 0.0f, den = 0.0f;
#pragma unroll
    for (int i = 0; i < 3; i++)
#pragma unroll
    for (int j = 0; j < 3; j++)
#pragma unroll
    for (int l = 0; l < 3; l++) {
        const int o = (i * 3 + j) * 3 + l;
        float dko = fmaxf(dk[o] + db, 0.0f);
        float rko = fmaxf(rk[o] + rb, 0.0f);
        float w   = fmaf(dko, rko, 1e-10f);
        float xv  = sx[(i * 3 + j) * SX_STRIDE + tid + l];  // col index (w+l-1)+1
        num = fmaf(w, xv, num);
        den += w;
    }

    out[m0 + tid] = num / den;
}

extern "C" void kernel_launch(void* const* d_in, const int* in_sizes, int n_in,
                              void* d_out, int out_size) {
    const float* x     = (const float*)d_in[0];
    const float* dom   = (const float*)d_in[1];
    const float* gui   = (const float*)d_in[2];
    const float* dom_w = (const float*)d_in[3];
    const float* dom_b = (const float*)d_in[4];
    const float* rng_w = (const float*)d_in[5];
    const float* rng_b = (const float*)d_in[6];
    float* out = (float*)d_out;

    cudaFuncSetAttribute(jbf_kernel, cudaFuncAttributeMaxDynamicSharedMemorySize,
                         SMEM_BYTES);

    const int grid = (Bn * Dout * Hn * Wn) / VOX;   // 4096 CTAs
    jbf_kernel<<<grid, VOX, SMEM_BYTES>>>(x, dom, gui, dom_w, dom_b, rng_w, rng_b, out);
}

// round 3
// speedup vs baseline: 1.2534x; 1.2534x over previous
#include <cuda_runtime.h>
#include <cstdint>

// Problem constants
static constexpr int Bn   = 2;
static constexpr int Din  = 18;
static constexpr int Dout = 16;
static constexpr int Hn   = 128;
static constexpr int Wn   = 128;
static constexpr int VOX  = 128;                 // voxels per CTA = threads per CTA
static constexpr int PL   = 25;                  // floats per 5x5 plane per voxel
static constexpr int STAGE_WORDS = VOX * PL;     // 3200 floats = 12800 B per stage
static constexpr int NBUF = 3;                   // triple buffer -> 1 barrier/stage
static constexpr int SX_STRIDE = 132;            // padded x-row stride
static constexpr int SX_WORDS  = 9 * SX_STRIDE;
static constexpr int SMEM_BYTES = (NBUF * STAGE_WORDS + SX_WORDS) * 4;  // ~43.2 KB

// ---------------- cp.async helpers ----------------
__device__ __forceinline__ void cp4(uint32_t saddr, const float* g) {
    asm volatile("cp.async.ca.shared.global [%0], [%1], 4;" :: "r"(saddr), "l"(g));
}
__device__ __forceinline__ void cp_commit() {
    asm volatile("cp.async.commit_group;" ::: "memory");
}
template <int N> __device__ __forceinline__ void cp_wait() {
    asm volatile("cp.async.wait_group %0;" :: "n"(N) : "memory");
}

// Issue one stage: plane p of `src` for this CTA's 128 voxels -> smem buffer.
// Thread t copies elements idx = t, t+128, ... (25 of 3200): coalesced in both
// global (mostly-contiguous 100B segments) and smem (strictly contiguous).
__device__ __forceinline__ void issue_stage(const float* __restrict__ src,
                                            long long m0, int p,
                                            uint32_t sbase_bytes,
                                            int tid, int r0, int c0) {
    const float* g = src + (m0 + r0) * 125 + p * 25 + c0;
    uint32_t s = sbase_bytes + (uint32_t)tid * 4u;
    int col = c0;
#pragma unroll
    for (int i = 0; i < PL; i++) {
        cp4(s, g);
        s += VOX * 4;
        col += 3;                       // 128 % 25 == 3
        if (col >= 25) { col -= 25; g += 728; }   // 6*125 - 22
        else           {            g += 628; }   // 5*125 + 3
    }
}

// Partial 5^3 -> 3^3 valid cross-correlation: contribution of plane P.
// sp = this thread's 25 floats for plane P (conflict-free: stride-25 rows).
template <int P>
__device__ __forceinline__ void conv_plane(const float* __restrict__ sp,
                                           const float (&wk)[27], float (&acc)[27]) {
#pragma unroll
    for (int q = 0; q < 5; q++)
#pragma unroll
    for (int r = 0; r < 5; r++) {
        float v = sp[q * 5 + r];
#pragma unroll
        for (int a = 0; a < 3; a++) {
            if (P - a < 0 || P - a > 2) continue;
#pragma unroll
            for (int bq = 0; bq < 3; bq++) {
                if (q - bq < 0 || q - bq > 2) continue;
#pragma unroll
                for (int cr = 0; cr < 3; cr++) {
                    if (r - cr < 0 || r - cr > 2) continue;
                    acc[(a * 3 + bq) * 3 + cr] =
                        fmaf(v, wk[((P - a) * 3 + (q - bq)) * 3 + (r - cr)],
                             acc[(a * 3 + bq) * 3 + cr]);
                }
            }
        }
    }
}

__global__ void __launch_bounds__(VOX, 4)
jbf_kernel(const float* __restrict__ x,
           const float* __restrict__ dom,
           const float* __restrict__ gui,
           const float* __restrict__ dom_w,
           const float* __restrict__ dom_b,
           const float* __restrict__ rng_w,
           const float* __restrict__ rng_b,
           float* __restrict__ out)
{
    extern __shared__ float smem[];
    float* sbuf = smem;                       // 3 stage buffers
    float* sx   = smem + NBUF * STAGE_WORDS;  // padded x rows

    const int tid = threadIdx.x;
    const int cta = blockIdx.x;
    const int h = cta & (Hn - 1);
    const int d = (cta >> 7) & (Dout - 1);
    const int b = cta >> 11;
    const long long m0 = (long long)cta * VOX;

    const int r0 = tid / 25, c0 = tid - r0 * 25;
    const uint32_t sm32 = (uint32_t)__cvta_generic_to_shared(smem);

    // ---- Pipeline prologue: prefetch stages 0 and 1 (dom planes 0,1) ----
    issue_stage(dom, m0, 0, sm32 + 0 * STAGE_WORDS * 4, tid, r0, c0); cp_commit();
    issue_stage(dom, m0, 1, sm32 + 1 * STAGE_WORDS * 4, tid, r0, c0); cp_commit();

    // ---- Stage x rows (small; overlaps with async stages) ----
    for (int idx = tid; idx < 9 * 130; idx += VOX) {
        int ij = idx / 130;
        int wp = idx - ij * 130;        // 0..129  -> w = wp-1
        int i = ij / 3, j = ij % 3;
        int hh = h + j - 1;
        int ww = wp - 1;
        float v = 0.0f;
        if (hh >= 0 && hh < Hn && ww >= 0 && ww < Wn)
            v = x[(((long long)b * Din + (d + i)) << 14) + (hh << 7) + ww];
        sx[ij * SX_STRIDE + wp] = v;
    }

    float wk[27];
#pragma unroll
    for (int t = 0; t < 27; t++) wk[t] = dom_w[t];

    float dk[27], rk[27];
#pragma unroll
    for (int o = 0; o < 27; o++) { dk[o] = 0.0f; rk[o] = 0.0f; }

    // One pipeline step: global stage ST (0..9). Waits stage ST, issues ST+2,
    // computes plane P into ACC. Single __syncthreads per stage.
#define PIPE_STEP(ST, P, ACC)                                                   \
    {                                                                           \
        cp_wait<1>(); __syncthreads();                                          \
        constexpr int nst = (ST) + 2;                                           \
        if (nst < 10) {                                                         \
            const float* nsrc = (nst < 5) ? dom : gui;                          \
            issue_stage(nsrc, m0, (nst < 5) ? nst : nst - 5,                    \
                        sm32 + (nst % NBUF) * STAGE_WORDS * 4, tid, r0, c0);    \
        }                                                                       \
        cp_commit();                                                            \
        conv_plane<P>(sbuf + ((ST) % NBUF) * STAGE_WORDS + tid * PL, wk, ACC);  \
    }

    // ---- Domain phase: stages 0..4 ----
    PIPE_STEP(0, 0, dk)
    PIPE_STEP(1, 1, dk)
    PIPE_STEP(2, 2, dk)
    PIPE_STEP(3, 3, dk)
    PIPE_STEP(4, 4, dk)

#pragma unroll
    for (int t = 0; t < 27; t++) wk[t] = rng_w[t];

    // ---- Range phase: stages 5..9 ----
    PIPE_STEP(5, 0, rk)
    PIPE_STEP(6, 1, rk)
    PIPE_STEP(7, 2, rk)
    PIPE_STEP(8, 3, rk)
    PIPE_STEP(9, 4, rk)
#undef PIPE_STEP

    // ---- Fuse: ReLU(conv+b), bilateral weight, weighted x-sum, normalize ----
    const float db = dom_b[0];
    const float rb = rng_b[0];
    float num = 0.0f, den = 0.0f;
#pragma unroll
    for (int i = 0; i < 3; i++)
#pragma unroll
    for (int j = 0; j < 3; j++)
#pragma unroll
    for (int l = 0; l < 3; l++) {
        const int o = (i * 3 + j) * 3 + l;
        float dko = fmaxf(dk[o] + db, 0.0f);
        float rko = fmaxf(rk[o] + rb, 0.0f);
        float w   = fmaf(dko, rko, 1e-10f);
        float xv  = sx[(i * 3 + j) * SX_STRIDE + tid + l];
        num = fmaf(w, xv, num);
        den += w;
    }

    out[m0 + tid] = num / den;
}

extern "C" void kernel_launch(void* const* d_in, const int* in_sizes, int n_in,
                              void* d_out, int out_size) {
    const float* x     = (const float*)d_in[0];
    const float* dom   = (const float*)d_in[1];
    const float* gui   = (const float*)d_in[2];
    const float* dom_w = (const float*)d_in[3];
    const float* dom_b = (const float*)d_in[4];
    const float* rng_w = (const float*)d_in[5];
    const float* rng_b = (const float*)d_in[6];
    float* out = (float*)d_out;

    cudaFuncSetAttribute(jbf_kernel, cudaFuncAttributeMaxDynamicSharedMemorySize,
                         SMEM_BYTES);

    const int grid = (Bn * Dout * Hn * Wn) / VOX;   // 4096 CTAs
    jbf_kernel<<<grid, VOX, SMEM_BYTES>>>(x, dom, gui, dom_w, dom_b, rng_w, rng_b, out);
}

// round 4
// speedup vs baseline: 1.8573x; 1.4818x over previous
#include <cuda_runtime.h>
#include <cstdint>

// Problem constants
static constexpr int Bn   = 2;
static constexpr int Din  = 18;
static constexpr int Dout = 16;
static constexpr int Hn   = 128;
static constexpr int Wn   = 128;
static constexpr int VOX  = 128;                 // voxels per CTA = one W row
static constexpr int ROWF = 125;                 // floats per voxel row (5^3)
static constexpr int BUF_WORDS = VOX * ROWF;     // 16000 floats = 64000 B
static constexpr int BUF_CHUNKS = BUF_WORDS / 4; // 4000 float4 chunks
static constexpr int SX_STRIDE = 132;            // padded x-row stride
static constexpr int SX_WORDS  = 9 * SX_STRIDE;
static constexpr int SMEM_BYTES = (BUF_WORDS + SX_WORDS) * 4;  // 68752 B

// ---------------- cp.async helpers (16B, L2-only) ----------------
__device__ __forceinline__ void cp16(uint32_t saddr, const void* g) {
    asm volatile("cp.async.cg.shared.global [%0], [%1], 16;" :: "r"(saddr), "l"(g));
}
__device__ __forceinline__ void cp_commit() {
    asm volatile("cp.async.commit_group;" ::: "memory");
}
__device__ __forceinline__ void cp_wait0() {
    asm volatile("cp.async.wait_group 0;" ::: "memory");
}

// Copy one full 64000B input chunk for this CTA into sbuf.
// Per warp-instruction: 32 lanes x 16B = 512B contiguous -> perfect coalescing.
__device__ __forceinline__ void stage_chunk(const float* __restrict__ src,
                                            long long m0, uint32_t sbase,
                                            int tid) {
    const float4* g = (const float4*)(src + m0 * ROWF) + tid;   // 16B-aligned
    uint32_t s = sbase + (uint32_t)tid * 16u;
#pragma unroll
    for (int i = 0; i < 31; i++) {
        cp16(s, g);
        s += VOX * 16;
        g += VOX;
    }
    if (tid < BUF_CHUNKS - 31 * VOX)   // 32 remaining chunks
        cp16(s, g);
}

// Full 5^3 -> 3^3 valid cross-correlation, input-stationary.
// 125 LDS.32 (conflict-free: lane word-stride 125 is odd) + 729 FMA.
__device__ __forceinline__ void conv_acc(const float* __restrict__ s,
                                         const float (&wk)[27], float (&acc)[27]) {
#pragma unroll
    for (int p = 0; p < 5; p++)
#pragma unroll
    for (int q = 0; q < 5; q++)
#pragma unroll
    for (int r = 0; r < 5; r++) {
        float v = s[p * 25 + q * 5 + r];
#pragma unroll
        for (int a = 0; a < 3; a++) {
            if (p - a < 0 || p - a > 2) continue;
#pragma unroll
            for (int bq = 0; bq < 3; bq++) {
                if (q - bq < 0 || q - bq > 2) continue;
#pragma unroll
                for (int cr = 0; cr < 3; cr++) {
                    if (r - cr < 0 || r - cr > 2) continue;
                    acc[(a * 3 + bq) * 3 + cr] =
                        fmaf(v, wk[((p - a) * 3 + (q - bq)) * 3 + (r - cr)],
                             acc[(a * 3 + bq) * 3 + cr]);
                }
            }
        }
    }
}

__global__ void __launch_bounds__(VOX, 3)
jbf_kernel(const float* __restrict__ x,
           const float* __restrict__ dom,
           const float* __restrict__ gui,
           const float* __restrict__ dom_w,
           const float* __restrict__ dom_b,
           const float* __restrict__ rng_w,
           const float* __restrict__ rng_b,
           float* __restrict__ out)
{
    extern __shared__ float smem[];
    float* sbuf = smem;                 // [VOX][125] one full input chunk
    float* sx   = smem + BUF_WORDS;     // [9][SX_STRIDE] padded x rows

    const int tid = threadIdx.x;
    const int cta = blockIdx.x;
    const int h = cta & (Hn - 1);
    const int d = (cta >> 7) & (Dout - 1);
    const int b = cta >> 11;
    const long long m0 = (long long)cta * VOX;

    const uint32_t sm32 = (uint32_t)__cvta_generic_to_shared(smem);

    // ---- Issue dom chunk copy first (hide latency behind sx staging) ----
    stage_chunk(dom, m0, sm32, tid);
    cp_commit();

    // ---- Stage x rows: planes d..d+2, rows h-1..h+1, cols -1..128 (zero-pad) ----
    for (int idx = tid; idx < 9 * 130; idx += VOX) {
        int ij = idx / 130;
        int wp = idx - ij * 130;        // 0..129  -> w = wp-1
        int i = ij / 3, j = ij % 3;
        int hh = h + j - 1;
        int ww = wp - 1;
        float v = 0.0f;
        if (hh >= 0 && hh < Hn && ww >= 0 && ww < Wn)
            v = x[(((long long)b * Din + (d + i)) << 14) + (hh << 7) + ww];
        sx[ij * SX_STRIDE + wp] = v;
    }

    float wk[27];
#pragma unroll
    for (int t = 0; t < 27; t++) wk[t] = dom_w[t];

    // ---- Phase 1: domain conv ----
    cp_wait0();
    __syncthreads();

    float dk[27];
#pragma unroll
    for (int o = 0; o < 27; o++) dk[o] = 0.0f;
    conv_acc(sbuf + tid * ROWF, wk, dk);

    __syncthreads();   // all reads of sbuf done before overwrite

    // ---- Phase 2: guide conv ----
    stage_chunk(gui, m0, sm32, tid);
    cp_commit();

#pragma unroll
    for (int t = 0; t < 27; t++) wk[t] = rng_w[t];

    cp_wait0();
    __syncthreads();

    float rk[27];
#pragma unroll
    for (int o = 0; o < 27; o++) rk[o] = 0.0f;
    conv_acc(sbuf + tid * ROWF, wk, rk);

    // ---- Fuse: ReLU(conv+b), bilateral weight, weighted x-sum, normalize ----
    const float db = dom_b[0];
    const float rb = rng_b[0];
    float num = 0.0f, den = 0.0f;
#pragma unroll
    for (int i = 0; i < 3; i++)
#pragma unroll
    for (int j = 0; j < 3; j++)
#pragma unroll
    for (int l = 0; l < 3; l++) {
        const int o = (i * 3 + j) * 3 + l;
        float dko = fmaxf(dk[o] + db, 0.0f);
        float rko = fmaxf(rk[o] + rb, 0.0f);
        float w   = fmaf(dko, rko, 1e-10f);
        float xv  = sx[(i * 3 + j) * SX_STRIDE + tid + l];
        num = fmaf(w, xv, num);
        den += w;
    }

    out[m0 + tid] = num / den;
}

extern "C" void kernel_launch(void* const* d_in, const int* in_sizes, int n_in,
                              void* d_out, int out_size) {
    const float* x     = (const float*)d_in[0];
    const float* dom   = (const float*)d_in[1];
    const float* gui   = (const float*)d_in[2];
    const float* dom_w = (const float*)d_in[3];
    const float* dom_b = (const float*)d_in[4];
    const float* rng_w = (const float*)d_in[5];
    const float* rng_b = (const float*)d_in[6];
    float* out = (float*)d_out;

    cudaFuncSetAttribute(jbf_kernel, cudaFuncAttributeMaxDynamicSharedMemorySize,
                         SMEM_BYTES);

    const int grid = (Bn * Dout * Hn * Wn) / VOX;   // 4096 CTAs
    jbf_kernel<<<grid, VOX, SMEM_BYTES>>>(x, dom, gui, dom_w, dom_b, rng_w, rng_b, out);
}

// round 5
// speedup vs baseline: 1.9530x; 1.0515x over previous
#include <cuda_runtime.h>
#include <cstdint>

// Problem constants
static constexpr int Bn   = 2;
static constexpr int Din  = 18;
static constexpr int Dout = 16;
static constexpr int Hn   = 128;
static constexpr int Wn   = 128;
static constexpr int VOX  = 128;                 // voxels per CTA = one W row
static constexpr int ROWF = 125;                 // floats per voxel row (5^3)
static constexpr int BUF_WORDS = VOX * ROWF;     // 16000 floats = 64000 B
static constexpr int WARP_VOX  = 32;
static constexpr int WARP_CHUNKS = WARP_VOX * ROWF / 4;  // 1000 float4 per warp
static constexpr int SMEM_BYTES = BUF_WORDS * 4;         // 64000 B

// ---------------- cp.async helpers (16B, L2-only) ----------------
__device__ __forceinline__ void cp16(uint32_t saddr, const void* g) {
    asm volatile("cp.async.cg.shared.global [%0], [%1], 16;"
                 :: "r"(saddr), "l"(g) : "memory");
}
__device__ __forceinline__ void cp_commit() {
    asm volatile("cp.async.commit_group;" ::: "memory");
}
__device__ __forceinline__ void cp_wait0() {
    asm volatile("cp.async.wait_group 0;" ::: "memory");
}

// Per-WARP copy: this warp's 32 voxels (16000B contiguous, 16B aligned).
// No cross-warp coordination needed.
__device__ __forceinline__ void stage_warp(const float* __restrict__ src,
                                           long long v_global0,   // first voxel of warp
                                           uint32_t sbase,        // smem byte addr of warp slice
                                           int lane) {
    const float4* g = (const float4*)(src + v_global0 * ROWF) + lane;
    uint32_t s = sbase + (uint32_t)lane * 16u;
#pragma unroll
    for (int i = 0; i < 31; i++) {
        cp16(s, g);
        s += 32 * 16;
        g += 32;
    }
    if (lane < WARP_CHUNKS - 31 * 32)   // 8 remaining chunks
        cp16(s, g);
}

// Full 5^3 -> 3^3 valid cross-correlation, input-stationary.
// 125 LDS.32 (conflict-free: lane word-stride 125 is odd) + 729 FMA.
__device__ __forceinline__ void conv_acc(const float* __restrict__ s,
                                         const float (&wk)[27], float (&acc)[27]) {
#pragma unroll
    for (int p = 0; p < 5; p++)
#pragma unroll
    for (int q = 0; q < 5; q++)
#pragma unroll
    for (int r = 0; r < 5; r++) {
        float v = s[p * 25 + q * 5 + r];
#pragma unroll
        for (int a = 0; a < 3; a++) {
            if (p - a < 0 || p - a > 2) continue;
#pragma unroll
            for (int bq = 0; bq < 3; bq++) {
                if (q - bq < 0 || q - bq > 2) continue;
#pragma unroll
                for (int cr = 0; cr < 3; cr++) {
                    if (r - cr < 0 || r - cr > 2) continue;
                    acc[(a * 3 + bq) * 3 + cr] =
                        fmaf(v, wk[((p - a) * 3 + (q - bq)) * 3 + (r - cr)],
                             acc[(a * 3 + bq) * 3 + cr]);
                }
            }
        }
    }
}

__global__ void __launch_bounds__(VOX, 3)
jbf_kernel(const float* __restrict__ x,
           const float* __restrict__ dom,
           const float* __restrict__ gui,
           const float* __restrict__ dom_w,
           const float* __restrict__ dom_b,
           const float* __restrict__ rng_w,
           const float* __restrict__ rng_b,
           float* __restrict__ out)
{
    extern __shared__ float sbuf[];     // [VOX][125], per-warp 32-voxel slices

    const int tid  = threadIdx.x;
    const int lane = tid & 31;
    const int v0   = tid & ~31;         // first voxel of this warp (CTA-local)
    const int cta  = blockIdx.x;
    const int h = cta & (Hn - 1);
    const int d = (cta >> 7) & (Dout - 1);
    const int b = cta >> 11;
    const long long m0 = (long long)cta * VOX;

    const uint32_t sm32 = (uint32_t)__cvta_generic_to_shared(sbuf);
    const uint32_t swarp = sm32 + (uint32_t)v0 * ROWF * 4u;
    const float* srow = sbuf + tid * ROWF;

    // ---- Phase 1: this warp stages + computes domain conv (no barriers) ----
    stage_warp(dom, m0 + v0, swarp, lane);
    cp_commit();

    float wk[27];
#pragma unroll
    for (int t = 0; t < 27; t++) wk[t] = dom_w[t];

    cp_wait0();
    __syncwarp();

    float dk[27];
#pragma unroll
    for (int o = 0; o < 27; o++) dk[o] = 0.0f;
    conv_acc(srow, wk, dk);

    // ---- Phase 2: restage with guide, compute range conv ----
    // (cp.async data cannot land before prior LDS complete: >=234cyc vs 29cyc)
    stage_warp(gui, m0 + v0, swarp, lane);
    cp_commit();

#pragma unroll
    for (int t = 0; t < 27; t++) wk[t] = rng_w[t];

    cp_wait0();
    __syncwarp();

    float rk[27];
#pragma unroll
    for (int o = 0; o < 27; o++) rk[o] = 0.0f;
    conv_acc(srow, wk, rk);

    // ---- Fused epilogue: ReLU, bilateral weight, weighted x-sum, normalize.
    //      x read directly (coalesced, L2-resident, mostly L1 hits). ----
    const float db = dom_b[0];
    const float rb = rng_b[0];
    const int w = tid;                  // W == VOX: thread == column
    float num = 0.0f, den = 0.0f;
#pragma unroll
    for (int i = 0; i < 3; i++)
#pragma unroll
    for (int j = 0; j < 3; j++) {
        const int hh = h + j - 1;
        const bool hok = (hh >= 0) && (hh < Hn);
        const long long base = (((long long)b * Din + (d + i)) << 14) + (hh << 7);
#pragma unroll
        for (int l = 0; l < 3; l++) {
            const int o = (i * 3 + j) * 3 + l;
            float dko = fmaxf(dk[o] + db, 0.0f);
            float rko = fmaxf(rk[o] + rb, 0.0f);
            float wt  = fmaf(dko, rko, 1e-10f);
            const int ww = w + l - 1;
            float xv = (hok && ww >= 0 && ww < Wn) ? x[base + ww] : 0.0f;
            num = fmaf(wt, xv, num);
            den += wt;
        }
    }

    out[m0 + tid] = num / den;
}

extern "C" void kernel_launch(void* const* d_in, const int* in_sizes, int n_in,
                              void* d_out, int out_size) {
    const float* x     = (const float*)d_in[0];
    const float* dom   = (const float*)d_in[1];
    const float* gui   = (const float*)d_in[2];
    const float* dom_w = (const float*)d_in[3];
    const float* dom_b = (const float*)d_in[4];
    const float* rng_w = (const float*)d_in[5];
    const float* rng_b = (const float*)d_in[6];
    float* out = (float*)d_out;

    cudaFuncSetAttribute(jbf_kernel, cudaFuncAttributeMaxDynamicSharedMemorySize,
                         SMEM_BYTES);

    const int grid = (Bn * Dout * Hn * Wn) / VOX;   // 4096 CTAs
    jbf_kernel<<<grid, VOX, SMEM_BYTES>>>(x, dom, gui, dom_w, dom_b, rng_w, rng_b, out);
}